// round 1
// baseline (speedup 1.0000x reference)
#include <cuda_runtime.h>
#include <cuda_bf16.h>
#include <math.h>

// Problem shape
#define BATCH 512
#define SEQ   256
#define DIM   512
#define NORM  0.044194173824159216f   // 1/sqrt(512)

// Scratch (static __device__ — no dynamic allocation allowed)
__device__ float g_M[DIM * DIM];                         // norm * Wq @ Wk^T
__device__ float g_G[(size_t)BATCH * SEQ * DIM];         // X @ M   (256 MB)
__device__ float g_Y2[(size_t)BATCH * 2 * DIM];          // per-half y contributions

// ---------------------------------------------------------------------------
// Kernel A: M = norm * (Wq @ Wk^T).  M[i][j] = norm * sum_e Wq[i,e]*Wk[j,e]
// ---------------------------------------------------------------------------
__global__ void __launch_bounds__(1024) wqwk_kernel(const float* __restrict__ Wq,
                                                    const float* __restrict__ Wk)
{
    __shared__ float aq[32][33];
    __shared__ float ak[32][33];
    int tx = threadIdx.x, ty = threadIdx.y;
    int row = blockIdx.y * 32 + ty;
    int col = blockIdx.x * 32 + tx;
    float acc = 0.0f;
    for (int kt = 0; kt < DIM; kt += 32) {
        aq[ty][tx] = Wq[row * DIM + kt + tx];
        ak[ty][tx] = Wk[(blockIdx.x * 32 + ty) * DIM + kt + tx];
        __syncthreads();
#pragma unroll
        for (int k = 0; k < 32; k++)
            acc += aq[ty][k] * ak[tx][k];
        __syncthreads();
    }
    g_M[row * DIM + col] = acc * NORM;
}

// ---------------------------------------------------------------------------
// Kernel B: G = Xflat @ M.   [131072,512] x [512,512] fp32 SGEMM
// BM=BN=128, BK=8, 256 threads, 8x8 microtile
// ---------------------------------------------------------------------------
__global__ void __launch_bounds__(256) gemm_G_kernel(const float* __restrict__ A,
                                                     float* __restrict__ C)
{
    const int K = DIM;
    __shared__ float As[8][128];
    __shared__ float Bs[8][128];
    int tid = threadIdx.x;
    int cCol = blockIdx.x;           // 0..3
    int cRow = blockIdx.y;           // 0..1023

    const float* Ab = A + (size_t)cRow * 128 * K;
    const float* Bb = g_M + cCol * 128;
    float*       Cb = C + (size_t)cRow * 128 * DIM + cCol * 128;

    int irA = tid >> 1;              // 0..127
    int icA = (tid & 1) * 4;         // 0 or 4
    int irB = tid >> 5;              // 0..7
    int icB = (tid & 31) * 4;        // 0..124
    int tr  = tid >> 4;              // 0..15
    int tc  = tid & 15;              // 0..15

    float acc[8][8];
#pragma unroll
    for (int i = 0; i < 8; i++)
#pragma unroll
        for (int j = 0; j < 8; j++) acc[i][j] = 0.0f;

    for (int kt = 0; kt < K; kt += 8) {
        float4 a4 = *(const float4*)(Ab + (size_t)irA * K + kt + icA);
        As[icA + 0][irA] = a4.x;
        As[icA + 1][irA] = a4.y;
        As[icA + 2][irA] = a4.z;
        As[icA + 3][irA] = a4.w;
        *(float4*)(&Bs[irB][icB]) = *(const float4*)(Bb + (size_t)(kt + irB) * DIM + icB);
        __syncthreads();
#pragma unroll
        for (int k = 0; k < 8; k++) {
            float4 m0 = *(const float4*)(&As[k][tr * 8]);
            float4 m1 = *(const float4*)(&As[k][tr * 8 + 4]);
            float4 n0 = *(const float4*)(&Bs[k][tc * 8]);
            float4 n1 = *(const float4*)(&Bs[k][tc * 8 + 4]);
            float rm[8] = {m0.x, m0.y, m0.z, m0.w, m1.x, m1.y, m1.z, m1.w};
            float rn[8] = {n0.x, n0.y, n0.z, n0.w, n1.x, n1.y, n1.z, n1.w};
#pragma unroll
            for (int i = 0; i < 8; i++)
#pragma unroll
                for (int j = 0; j < 8; j++)
                    acc[i][j] += rm[i] * rn[j];
        }
        __syncthreads();
    }
#pragma unroll
    for (int i = 0; i < 8; i++) {
        *(float4*)(Cb + (size_t)(tr * 8 + i) * DIM + tc * 8) =
            make_float4(acc[i][0], acc[i][1], acc[i][2], acc[i][3]);
        *(float4*)(Cb + (size_t)(tr * 8 + i) * DIM + tc * 8 + 4) =
            make_float4(acc[i][4], acc[i][5], acc[i][6], acc[i][7]);
    }
}

// ---------------------------------------------------------------------------
// Kernel C: per (batch, half) fused:
//   S[128x256] = G_chunk @ X_b^T ; row softmax ; w_part = colsum(attn) ;
//   y_part[d]  = sum_m w_part[m] * X_b[m,d]  -> g_Y2[(2b+half)*512 + d]
// 512 threads: warp w owns rows w*8..+7, lane owns cols lane*8..+7
// ---------------------------------------------------------------------------
__global__ void __launch_bounds__(512) attn_kernel(const float* __restrict__ X,
                                                   float* __restrict__ Y2)
{
    int bx   = blockIdx.x;        // 0..1023
    int b    = bx >> 1;
    int half = bx & 1;
    int tid  = threadIdx.x;
    int warp = tid >> 5;
    int lane = tid & 31;

    __shared__ float Gs[16][132];
    __shared__ float Xs[16][260];
    __shared__ float wpart[16][256];
    __shared__ float w_s[256];

    const float* Gb = g_G + ((size_t)b * SEQ + half * 128) * DIM;
    const float* Xb = X + (size_t)b * SEQ * DIM;

    float acc[8][8];
#pragma unroll
    for (int i = 0; i < 8; i++)
#pragma unroll
        for (int j = 0; j < 8; j++) acc[i][j] = 0.0f;

    int r0 = warp * 8;
    int c0 = lane * 8;
    int gr = tid >> 2;            // 0..127
    int gk = (tid & 3) * 4;       // 0,4,8,12
    int xm = tid >> 1;            // 0..255
    int xk = (tid & 1) * 8;       // 0 or 8

    for (int kt = 0; kt < DIM; kt += 16) {
        float4 g4 = *(const float4*)(Gb + (size_t)gr * DIM + kt + gk);
        Gs[gk + 0][gr] = g4.x;
        Gs[gk + 1][gr] = g4.y;
        Gs[gk + 2][gr] = g4.z;
        Gs[gk + 3][gr] = g4.w;
        float4 xa = *(const float4*)(Xb + (size_t)xm * DIM + kt + xk);
        float4 xb = *(const float4*)(Xb + (size_t)xm * DIM + kt + xk + 4);
        Xs[xk + 0][xm] = xa.x;
        Xs[xk + 1][xm] = xa.y;
        Xs[xk + 2][xm] = xa.z;
        Xs[xk + 3][xm] = xa.w;
        Xs[xk + 4][xm] = xb.x;
        Xs[xk + 5][xm] = xb.y;
        Xs[xk + 6][xm] = xb.z;
        Xs[xk + 7][xm] = xb.w;
        __syncthreads();
#pragma unroll
        for (int k = 0; k < 16; k++) {
            float4 g0 = *(const float4*)(&Gs[k][r0]);
            float4 g1 = *(const float4*)(&Gs[k][r0 + 4]);
            float4 x0 = *(const float4*)(&Xs[k][c0]);
            float4 x1 = *(const float4*)(&Xs[k][c0 + 4]);
            float rm[8] = {g0.x, g0.y, g0.z, g0.w, g1.x, g1.y, g1.z, g1.w};
            float rn[8] = {x0.x, x0.y, x0.z, x0.w, x1.x, x1.y, x1.z, x1.w};
#pragma unroll
            for (int i = 0; i < 8; i++)
#pragma unroll
                for (int j = 0; j < 8; j++)
                    acc[i][j] += rm[i] * rn[j];
        }
        __syncthreads();
    }

    // Row softmax + column-sum accumulation (each warp handles its 8 rows)
    float colacc[8];
#pragma unroll
    for (int j = 0; j < 8; j++) colacc[j] = 0.0f;

#pragma unroll
    for (int i = 0; i < 8; i++) {
        float rmax = acc[i][0];
#pragma unroll
        for (int j = 1; j < 8; j++) rmax = fmaxf(rmax, acc[i][j]);
#pragma unroll
        for (int o = 16; o > 0; o >>= 1)
            rmax = fmaxf(rmax, __shfl_xor_sync(0xffffffffu, rmax, o));
        float e[8], rsum = 0.0f;
#pragma unroll
        for (int j = 0; j < 8; j++) {
            e[j] = __expf(acc[i][j] - rmax);
            rsum += e[j];
        }
#pragma unroll
        for (int o = 16; o > 0; o >>= 1)
            rsum += __shfl_xor_sync(0xffffffffu, rsum, o);
        float inv = 1.0f / rsum;
#pragma unroll
        for (int j = 0; j < 8; j++) colacc[j] += e[j] * inv;
    }
#pragma unroll
    for (int j = 0; j < 8; j++) wpart[warp][c0 + j] = colacc[j];
    __syncthreads();

    if (tid < 256) {
        float s = 0.0f;
#pragma unroll
        for (int w = 0; w < 16; w++) s += wpart[w][tid];
        w_s[tid] = s;
    }
    __syncthreads();

    // y_part[d] = sum_m w_s[m] * X_b[m, d]
    {
        int d = tid;               // 0..511
        float y = 0.0f;
#pragma unroll 4
        for (int m = 0; m < SEQ; m++)
            y = fmaf(w_s[m], Xb[(size_t)m * DIM + d], y);
        Y2[(size_t)bx * DIM + d] = y;
    }
}

// ---------------------------------------------------------------------------
// Kernel D: merged = Y @ Wv, where Y[b] = Y2[2b] + Y2[2b+1]
// ---------------------------------------------------------------------------
__global__ void __launch_bounds__(1024) final_gemm_kernel(const float* __restrict__ Wv,
                                                          float* __restrict__ out)
{
    __shared__ float ys[32][33];
    __shared__ float ws[32][33];
    int tx = threadIdx.x, ty = threadIdx.y;
    int row = blockIdx.y * 32 + ty;      // batch
    int col = blockIdx.x * 32 + tx;      // output dim
    float acc = 0.0f;
    for (int kt = 0; kt < DIM; kt += 32) {
        ys[ty][tx] = g_Y2[(size_t)(2 * row) * DIM + kt + tx] +
                     g_Y2[(size_t)(2 * row + 1) * DIM + kt + tx];
        ws[ty][tx] = Wv[(size_t)(kt + ty) * DIM + col];
        __syncthreads();
#pragma unroll
        for (int k = 0; k < 32; k++)
            acc += ys[ty][k] * ws[k][tx];
        __syncthreads();
    }
    out[(size_t)row * DIM + col] = acc;
}

// ---------------------------------------------------------------------------
// Launch
// ---------------------------------------------------------------------------
extern "C" void kernel_launch(void* const* d_in, const int* in_sizes, int n_in,
                              void* d_out, int out_size)
{
    const float* X  = (const float*)d_in[0];   // [512,256,512]
    const float* Wq = (const float*)d_in[1];   // [512,512]
    const float* Wk = (const float*)d_in[2];
    const float* Wv = (const float*)d_in[3];
    float* out = (float*)d_out;                // [512,512]

    float* G;
    float* Y2;
    cudaGetSymbolAddress((void**)&G,  g_G);
    cudaGetSymbolAddress((void**)&Y2, g_Y2);

    // A: M = norm * Wq @ Wk^T
    wqwk_kernel<<<dim3(16, 16), dim3(32, 32)>>>(Wq, Wk);
    // B: G = Xflat @ M
    gemm_G_kernel<<<dim3(4, 1024), 256>>>(X, G);
    // C: fused scores/softmax/colsum/y per (batch, half)
    attn_kernel<<<1024, 512>>>(X, Y2);
    // D: merged = (Y2[2b]+Y2[2b+1]) @ Wv
    final_gemm_kernel<<<dim3(16, 16), dim3(32, 32)>>>(Wv, out);
}